// round 2
// baseline (speedup 1.0000x reference)
#include <cuda_runtime.h>

// FurthestPoint sampling, B=16, N=65536, npoint=2048. sm_100a.
// 8 persistent blocks/batch, all point state in registers.
// Per-iter: reg compute -> redux/ballot warp argmax -> one __syncthreads ->
// warp0 block argmax -> t0 stg packed(u64)+red.release counter ->
// ALL threads tight-spin ld.acquire, gather 8 packed slots, u64-max, load point.

#define BATCHES 16
#define NPTS    65536
#define NPOINT  2048
#define NBLK    8
#define THREADS 1024
#define PTS     8
#define NWARP   (THREADS / 32)

__device__ unsigned long long g_slot[BATCHES][2][NBLK];
__device__ unsigned           g_arrive[BATCHES];

__global__ void fps_init() {
    if (threadIdx.x < BATCHES) g_arrive[threadIdx.x] = 0u;
}

__device__ __forceinline__ unsigned ld_acquire(const unsigned* p) {
    unsigned v;
    asm volatile("ld.acquire.gpu.global.u32 %0, [%1];" : "=r"(v) : "l"(p) : "memory");
    return v;
}
__device__ __forceinline__ void red_release_add(unsigned* p, unsigned v) {
    asm volatile("red.release.gpu.global.add.u32 [%0], %1;" :: "l"(p), "r"(v) : "memory");
}
__device__ __forceinline__ unsigned long long ld_cg64(const unsigned long long* p) {
    unsigned long long v;
    asm volatile("ld.global.cg.u64 %0, [%1];" : "=l"(v) : "l"(p) : "memory");
    return v;
}
__device__ __forceinline__ void st_cg64(unsigned long long* p, unsigned long long v) {
    asm volatile("st.global.cg.u64 [%0], %1;" :: "l"(p), "l"(v) : "memory");
}

__global__ void __launch_bounds__(THREADS, 1)
fps_kernel(const float* __restrict__ xyz, float* __restrict__ out)
{
    const int b    = blockIdx.x / NBLK;
    const int blk  = blockIdx.x - b * NBLK;
    const int t    = threadIdx.x;
    const int lane = t & 31;
    const int wid  = t >> 5;

    const float* __restrict__ base = xyz + (size_t)b * NPTS * 3;
    float* __restrict__ out_idx = out;                              // (B, NPOINT) idx as float
    float* __restrict__ out_smp = out + (size_t)BATCHES * NPOINT;   // (B, 3, NPOINT)

    __shared__ unsigned long long s_w[NWARP];

    // Load this thread's 8 points into registers.
    const int pbase = (blk * THREADS + t) * PTS;
    float x[PTS], y[PTS], z[PTS], s[PTS];
#pragma unroll
    for (int k = 0; k < PTS; k++) {
        const float* q = base + (size_t)(pbase + k) * 3;
        x[k] = q[0]; y[k] = q[1]; z[k] = q[2];
        s[k] = 1e10f;
    }

    float px = base[0], py = base[1], pz = base[2];
    if (blk == 0 && t == 0) {
        out_idx[(size_t)b * NPOINT] = 0.0f;
        out_smp[((size_t)b * 3 + 0) * NPOINT] = px;
        out_smp[((size_t)b * 3 + 1) * NPOINT] = py;
        out_smp[((size_t)b * 3 + 2) * NPOINT] = pz;
    }

    unsigned* arr = &g_arrive[b];

    for (int j = 1; j < NPOINT; j++) {
        // ---- distance update + per-thread max (value only, registers) ----
        float m = -1.0f;
#pragma unroll
        for (int k = 0; k < PTS; k++) {
            float dx = x[k] - px, dy = y[k] - py, dz = z[k] - pz;
            float d  = __fmaf_rn(dz, dz, __fmaf_rn(dy, dy, __fmul_rn(dx, dx)));
            float sn = fminf(s[k], d);
            s[k] = sn;
            m = fmaxf(m, sn);
        }

        // ---- warp argmax: redux on value (positive float == monotone u32),
        //      lowest lane with max value == lowest index ----
        unsigned mu   = __float_as_uint(m);
        unsigned wmax = __reduce_max_sync(0xffffffffu, mu);
        unsigned ball = __ballot_sync(0xffffffffu, mu == wmax);
        int      src  = __ffs(ball) - 1;
        float    mf   = __uint_as_float(wmax);
        int kk = 0;
#pragma unroll
        for (int k = PTS - 1; k >= 0; k--)
            if (s[k] == mf) kk = k;                // lowest k with the max
        int idx = __shfl_sync(0xffffffffu, pbase + kk, src);

        if (lane == 0)
            s_w[wid] = ((unsigned long long)wmax << 32) | (unsigned)(~idx);
        __syncthreads();

        // ---- block argmax in warp 0 (lane order == warp order == index order) ----
        if (wid == 0) {
            unsigned long long pw = s_w[lane];
            unsigned v32  = (unsigned)(pw >> 32);
            unsigned bmax = __reduce_max_sync(0xffffffffu, v32);
            unsigned bb   = __ballot_sync(0xffffffffu, v32 == bmax);
            int      bsrc = __ffs(bb) - 1;
            unsigned long long bw = __shfl_sync(0xffffffffu, pw, bsrc);
            if (lane == 0) {
                st_cg64(&g_slot[b][j & 1][blk], bw);
                red_release_add(arr, 1u);
            }
        }

        // ---- all threads: tight poll, gather 8 packed slots, u64 max ----
        const unsigned target = (unsigned)j * NBLK;
        while (ld_acquire(arr) < target) {}

        const unsigned long long* slot = &g_slot[b][j & 1][0];
        unsigned long long best = ld_cg64(&slot[0]);
#pragma unroll
        for (int i = 1; i < NBLK; i++) {
            unsigned long long v = ld_cg64(&slot[i]);
            if (v > best) best = v;
        }
        int wi = (int)(~(unsigned)best);

        const float* q = base + (size_t)wi * 3;   // immutable input, L1/L2 ok
        px = q[0]; py = q[1]; pz = q[2];

        if (blk == 0 && t == 0) {
            out_idx[(size_t)b * NPOINT + j] = (float)wi;
            out_smp[((size_t)b * 3 + 0) * NPOINT + j] = px;
            out_smp[((size_t)b * 3 + 1) * NPOINT + j] = py;
            out_smp[((size_t)b * 3 + 2) * NPOINT + j] = pz;
        }
    }
}

extern "C" void kernel_launch(void* const* d_in, const int* in_sizes, int n_in,
                              void* d_out, int out_size) {
    (void)in_sizes; (void)n_in; (void)out_size;
    const float* xyz = (const float*)d_in[0];
    float* out = (float*)d_out;
    fps_init<<<1, 32>>>();
    fps_kernel<<<BATCHES * NBLK, THREADS>>>(xyz, out);
}

// round 5
// speedup vs baseline: 4.0151x; 4.0151x over previous
#include <cuda_runtime.h>

// FurthestPoint sampling, B=16, N=65536, npoint=2048. sm_100a.
// 8 persistent blocks/batch, 512 thr x 16 pts/thread in registers.
// Inter-block sync: R1-proven red.release counter + ld.acquire tight poll,
// polled by warp0 only. Packed u64 partials, double-buffered.

#define BATCHES 16
#define NPTS    65536
#define NPOINT  2048
#define NBLK    8
#define THREADS 512
#define PTS     16
#define NWARP   (THREADS / 32)

__device__ unsigned long long g_slot[BATCHES][2][NBLK];  // val<<32 | ~idx
__device__ unsigned           g_arrive[BATCHES];

__global__ void fps_init() {
    if (threadIdx.x < BATCHES) g_arrive[threadIdx.x] = 0u;
}

__device__ __forceinline__ unsigned ld_acquire(const unsigned* p) {
    unsigned v;
    asm volatile("ld.acquire.gpu.global.u32 %0, [%1];" : "=r"(v) : "l"(p) : "memory");
    return v;
}
__device__ __forceinline__ void red_release_add(unsigned* p, unsigned v) {
    asm volatile("red.release.gpu.global.add.u32 [%0], %1;" :: "l"(p), "r"(v) : "memory");
}
__device__ __forceinline__ unsigned long long ld_cg64(const unsigned long long* p) {
    unsigned long long v;
    asm volatile("ld.global.cg.u64 %0, [%1];" : "=l"(v) : "l"(p) : "memory");
    return v;
}
__device__ __forceinline__ void st_cg64(unsigned long long* p, unsigned long long v) {
    asm volatile("st.global.cg.u64 [%0], %1;" :: "l"(p), "l"(v) : "memory");
}

__global__ void __launch_bounds__(THREADS, 1)
fps_kernel(const float* __restrict__ xyz, float* __restrict__ out)
{
    const int b    = blockIdx.x / NBLK;
    const int blk  = blockIdx.x - b * NBLK;
    const int t    = threadIdx.x;
    const int lane = t & 31;
    const int wid  = t >> 5;

    const float* __restrict__ base = xyz + (size_t)b * NPTS * 3;
    float* __restrict__ out_idx = out;                              // (B, NPOINT) idx as float
    float* __restrict__ out_smp = out + (size_t)BATCHES * NPOINT;   // (B, 3, NPOINT)

    __shared__ unsigned s_v[NWARP];
    __shared__ int      s_i[NWARP];
    __shared__ float    s_p[3];

    const int pbase = (blk * THREADS + t) * PTS;
    float x[PTS], y[PTS], z[PTS], s[PTS];
#pragma unroll
    for (int k = 0; k < PTS; k++) {
        const float* q = base + (size_t)(pbase + k) * 3;
        x[k] = q[0]; y[k] = q[1]; z[k] = q[2];
        s[k] = 1e10f;
    }

    float px = base[0], py = base[1], pz = base[2];
    if (blk == 0 && t == 0) {
        out_idx[(size_t)b * NPOINT] = 0.0f;
        out_smp[((size_t)b * 3 + 0) * NPOINT] = px;
        out_smp[((size_t)b * 3 + 1) * NPOINT] = py;
        out_smp[((size_t)b * 3 + 2) * NPOINT] = pz;
    }

    unsigned* arr = &g_arrive[b];

    for (int j = 1; j < NPOINT; j++) {
        // ---- distance update (registers only) ----
#pragma unroll
        for (int k = 0; k < PTS; k++) {
            float dx = x[k] - px, dy = y[k] - py, dz = z[k] - pz;
            float d  = __fmaf_rn(dz, dz, __fmaf_rn(dy, dy, __fmul_rn(dx, dx)));
            s[k] = fminf(s[k], d);
        }
        // per-thread max as a tree (short dependent path)
        float t0 = fmaxf(fmaxf(s[0],  s[1]),  fmaxf(s[2],  s[3]));
        float t1 = fmaxf(fmaxf(s[4],  s[5]),  fmaxf(s[6],  s[7]));
        float t2 = fmaxf(fmaxf(s[8],  s[9]),  fmaxf(s[10], s[11]));
        float t3 = fmaxf(fmaxf(s[12], s[13]), fmaxf(s[14], s[15]));
        float m  = fmaxf(fmaxf(t0, t1), fmaxf(t2, t3));

        // ---- warp argmax: redux on value, lowest-lane tie break == lowest index ----
        unsigned mu   = __float_as_uint(m);
        unsigned wmax = __reduce_max_sync(0xffffffffu, mu);
        unsigned ball = __ballot_sync(0xffffffffu, mu == wmax);
        int      src  = __ffs(ball) - 1;
        float    mf   = __uint_as_float(wmax);
        int kk = 0;
#pragma unroll
        for (int k = PTS - 1; k >= 0; k--)
            if (s[k] == mf) kk = k;                    // lowest k with max
        int idx = __shfl_sync(0xffffffffu, pbase + kk, src);

        if (lane == 0) { s_v[wid] = wmax; s_i[wid] = idx; }
        __syncthreads();

        if (wid == 0) {
            // ---- block argmax over 16 warp winners (lane order == index order) ----
            int sl = lane & (NWARP - 1);
            unsigned v  = s_v[sl];
            int      bi = s_i[sl];
            unsigned bmax = __reduce_max_sync(0xffffffffu, v);
            unsigned bb   = __ballot_sync(0xffffffffu, v == bmax);
            int      bsrc = __ffs(bb) - 1;
            int      widx = __shfl_sync(0xffffffffu, bi, bsrc);

            const int buf = j & 1;
            unsigned long long* slot = &g_slot[b][buf][0];
            if (lane == 0) {
                st_cg64(&slot[blk], ((unsigned long long)bmax << 32)
                                    | (unsigned)(~widx));
                red_release_add(arr, 1u);   // release: orders the slot store
            }

            // ---- tight poll (warp-uniform broadcast load, 8 warps/batch) ----
            const unsigned target = (unsigned)j * NBLK;
            while (ld_acquire(arr) < target) {}

            // ---- lane i reads slot i&7, cross-block u32 argmax + ~idx tiebreak ----
            unsigned long long v64 = ld_cg64(&slot[lane & (NBLK - 1)]);
            unsigned val32 = (unsigned)(v64 >> 32);
            unsigned gmax  = __reduce_max_sync(0xffffffffu, val32);
            // among slots with val==gmax pick largest ~idx (== lowest idx)
            unsigned low   = (val32 == gmax) ? (unsigned)v64 : 0u;
            unsigned glow  = __reduce_max_sync(0xffffffffu, low);
            int wi = (int)(~glow) & 0xffff;
            wi = (int)(~glow);

            const float* q = base + (size_t)wi * 3;    // warp-uniform broadcast load
            px = q[0]; py = q[1]; pz = q[2];
            if (lane == 0) {
                s_p[0] = px; s_p[1] = py; s_p[2] = pz;
                if (blk == 0) {
                    out_idx[(size_t)b * NPOINT + j] = (float)wi;
                    out_smp[((size_t)b * 3 + 0) * NPOINT + j] = px;
                    out_smp[((size_t)b * 3 + 1) * NPOINT + j] = py;
                    out_smp[((size_t)b * 3 + 2) * NPOINT + j] = pz;
                }
            }
        }
        __syncthreads();
        px = s_p[0]; py = s_p[1]; pz = s_p[2];
    }
}

extern "C" void kernel_launch(void* const* d_in, const int* in_sizes, int n_in,
                              void* d_out, int out_size) {
    (void)in_sizes; (void)n_in; (void)out_size;
    const float* xyz = (const float*)d_in[0];
    float* out = (float*)d_out;
    fps_init<<<1, 32>>>();
    fps_kernel<<<BATCHES * NBLK, THREADS>>>(xyz, out);
}